// round 2
// baseline (speedup 1.0000x reference)
#include <cuda_runtime.h>
#include <cuda_bf16.h>

// Problem constants
#define B_BATCH 64
#define T_LEN   2048
#define F_DIM   256
#define BT      (B_BATCH * T_LEN)   // 131072

// Phase-1 tiling
#define M_TILE   128
#define G_CHUNK  64
#define XS_STRIDE 260               // 260 % 32 == 4 -> A-frag loads conflict-free
#define WS_STRIDE 72                // 72  % 32 == 8 -> B-frag loads conflict-free
#define X_SMEM_ELEMS (M_TILE * XS_STRIDE)   // 33280
#define W_SMEM_ELEMS (F_DIM * WS_STRIDE)    // 18432
#define SMEM_FLOATS  (X_SMEM_ELEMS + W_SMEM_ELEMS + 2 * G_CHUNK)
#define SMEM_BYTES   (SMEM_FLOATS * 4)      // 207,360 bytes

// Scratch (no allocations allowed -> device globals)
__device__ float g_ait[BT];
__device__ float g_a[BT];
__device__ float g_part[16 * B_BATCH * F_DIM];

__device__ __forceinline__ float to_tf32(float x) {
    float r;
    asm("cvt.rna.tf32.f32 %0, %1;" : "=f"(r) : "f"(x));
    return r;
}

// ---------------------------------------------------------------------------
// Phase 1: ait[row] = sum_g tanh( (x@W)[row,g] + b[g] ) * u[g]
// CTA: 128 rows, x tile resident in smem, W streamed in 4 chunks of 64 cols.
// mma.sync m16n8k8 tf32. Per warp: 16 rows x 64 cols per chunk.
// ---------------------------------------------------------------------------
__global__ void __launch_bounds__(256) k_ait(
    const float* __restrict__ x, const float* __restrict__ W,
    const float* __restrict__ bias, const float* __restrict__ u)
{
    extern __shared__ float sm[];
    float* xs = sm;                       // [128][260]
    float* ws = sm + X_SMEM_ELEMS;        // [256][72]
    float* us = ws + W_SMEM_ELEMS;        // [64]
    float* bs = us + G_CHUNK;             // [64]

    const int tid  = threadIdx.x;
    const int lane = tid & 31;
    const int wid  = tid >> 5;
    const int q    = lane >> 2;   // groupID
    const int m    = lane & 3;    // threadID-in-group
    const int mrow = wid * 16;
    const long row0 = (long)blockIdx.x * M_TILE;

    // Load x tile (fully contiguous 128KB block), convert to tf32.
    {
        const float4* xg = reinterpret_cast<const float4*>(x + row0 * F_DIM);
        #pragma unroll
        for (int i = 0; i < 32; i++) {
            int flat = i * 256 + tid;             // float4 index 0..8191
            int r  = flat >> 6;                   // 64 float4 per row
            int c4 = flat & 63;
            float4 v = xg[flat];
            float* p = xs + r * XS_STRIDE + c4 * 4;
            p[0] = to_tf32(v.x); p[1] = to_tf32(v.y);
            p[2] = to_tf32(v.z); p[3] = to_tf32(v.w);
        }
    }

    float sA = 0.f, sB = 0.f;   // per-thread partial of tanh()*u for 2 rows

    for (int gc = 0; gc < 4; ++gc) {
        const int g0 = gc * G_CHUNK;
        __syncthreads();   // protects xs stores (iter 0) / ws reads (iter>0)

        // Load W[:, g0:g0+64] (hot in L2), convert to tf32, [k][n] layout.
        #pragma unroll
        for (int i = 0; i < 16; i++) {
            int flat = i * 256 + tid;             // float4 index 0..4095
            int f  = flat >> 4;                   // 16 float4 per row
            int c4 = flat & 15;
            const float4* wp = reinterpret_cast<const float4*>(W + f * F_DIM + g0);
            float4 v = wp[c4];
            float* p = ws + f * WS_STRIDE + c4 * 4;
            p[0] = to_tf32(v.x); p[1] = to_tf32(v.y);
            p[2] = to_tf32(v.z); p[3] = to_tf32(v.w);
        }
        if (tid < G_CHUNK) {
            us[tid] = u[g0 + tid];
            bs[tid] = bias[g0 + tid];
        }
        __syncthreads();

        float acc[8][4];
        #pragma unroll
        for (int nt = 0; nt < 8; nt++)
            #pragma unroll
            for (int i = 0; i < 4; i++) acc[nt][i] = 0.f;

        #pragma unroll 4
        for (int k0 = 0; k0 < F_DIM; k0 += 8) {
            const float* ab = xs + (mrow + q) * XS_STRIDE + k0 + m;
            unsigned a0 = __float_as_uint(ab[0]);
            unsigned a1 = __float_as_uint(ab[8 * XS_STRIDE]);
            unsigned a2 = __float_as_uint(ab[4]);
            unsigned a3 = __float_as_uint(ab[8 * XS_STRIDE + 4]);
            const float* bb = ws + (k0 + m) * WS_STRIDE + q;
            #pragma unroll
            for (int nt = 0; nt < 8; nt++) {
                unsigned b0 = __float_as_uint(bb[nt * 8]);
                unsigned b1 = __float_as_uint(bb[4 * WS_STRIDE + nt * 8]);
                asm volatile(
                    "mma.sync.aligned.m16n8k8.row.col.f32.tf32.tf32.f32 "
                    "{%0,%1,%2,%3}, {%4,%5,%6,%7}, {%8,%9}, {%0,%1,%2,%3};"
                    : "+f"(acc[nt][0]), "+f"(acc[nt][1]),
                      "+f"(acc[nt][2]), "+f"(acc[nt][3])
                    : "r"(a0), "r"(a1), "r"(a2), "r"(a3), "r"(b0), "r"(b1));
            }
        }

        // Epilogue: tanh(z + b) * u, accumulate per-row partials.
        #pragma unroll
        for (int nt = 0; nt < 8; nt++) {
            int col = nt * 8 + 2 * m;
            sA += tanhf(acc[nt][0] + bs[col])     * us[col];
            sA += tanhf(acc[nt][1] + bs[col + 1]) * us[col + 1];
            sB += tanhf(acc[nt][2] + bs[col])     * us[col];
            sB += tanhf(acc[nt][3] + bs[col + 1]) * us[col + 1];
        }
    }

    // Quad reduce (lanes 4q..4q+3 hold disjoint columns of the same rows).
    sA += __shfl_xor_sync(0xffffffffu, sA, 1);
    sA += __shfl_xor_sync(0xffffffffu, sA, 2);
    sB += __shfl_xor_sync(0xffffffffu, sB, 1);
    sB += __shfl_xor_sync(0xffffffffu, sB, 2);
    if (m == 0) {
        long r = row0 + mrow + q;
        g_ait[r]     = sA;
        g_ait[r + 8] = sB;
    }
}

// ---------------------------------------------------------------------------
// Phase 2: a[b,t] = exp(ait)/(sum_t exp(ait) + 1e-7)   (reference: no max-sub)
// ---------------------------------------------------------------------------
__global__ void __launch_bounds__(256) k_softmax()
{
    __shared__ float ex[T_LEN];
    __shared__ float red[256];
    const int b = blockIdx.x, tid = threadIdx.x;
    float s = 0.f;
    for (int i = tid; i < T_LEN; i += 256) {
        float e = expf(g_ait[b * T_LEN + i]);
        ex[i] = e;
        s += e;
    }
    red[tid] = s;
    __syncthreads();
    for (int off = 128; off > 0; off >>= 1) {
        if (tid < off) red[tid] += red[tid + off];
        __syncthreads();
    }
    float inv = 1.f / (red[0] + 1e-7f);
    for (int i = tid; i < T_LEN; i += 256)
        g_a[b * T_LEN + i] = ex[i] * inv;
}

// ---------------------------------------------------------------------------
// Phase 3: partial weighted sums over 128-t chunks (deterministic, no atomics)
// ---------------------------------------------------------------------------
__global__ void __launch_bounds__(256) k_wsum(const float* __restrict__ x)
{
    __shared__ float as[128];
    const int chunk = blockIdx.x, b = blockIdx.y, tid = threadIdx.x;
    const int t0 = chunk * 128;
    if (tid < 128) as[tid] = g_a[b * T_LEN + t0 + tid];
    __syncthreads();
    const float* xb = x + ((long)(b * T_LEN + t0)) * F_DIM + tid;
    float s = 0.f;
    #pragma unroll 8
    for (int tt = 0; tt < 128; tt++)
        s += xb[(long)tt * F_DIM] * as[tt];
    g_part[(chunk * B_BATCH + b) * F_DIM + tid] = s;
}

// ---------------------------------------------------------------------------
// Phase 4: reduce 16 partials -> out[b,f]
// ---------------------------------------------------------------------------
__global__ void __launch_bounds__(256) k_red(float* __restrict__ out)
{
    const int b = blockIdx.x, tid = threadIdx.x;
    float s = 0.f;
    #pragma unroll
    for (int c = 0; c < 16; c++)
        s += g_part[(c * B_BATCH + b) * F_DIM + tid];
    out[b * F_DIM + tid] = s;
}

// ---------------------------------------------------------------------------
extern "C" void kernel_launch(void* const* d_in, const int* in_sizes, int n_in,
                              void* d_out, int out_size)
{
    const float* x    = (const float*)d_in[0];
    const float* W    = (const float*)d_in[1];
    const float* bias = (const float*)d_in[2];
    const float* u    = (const float*)d_in[3];
    float* out = (float*)d_out;

    cudaFuncSetAttribute(k_ait, cudaFuncAttributeMaxDynamicSharedMemorySize, SMEM_BYTES);

    k_ait<<<BT / M_TILE, 256, SMEM_BYTES>>>(x, W, bias, u);
    k_softmax<<<B_BATCH, 256>>>();
    k_wsum<<<dim3(16, B_BATCH), 256>>>(x);
    k_red<<<B_BATCH, 256>>>(out);
}

// round 5
// speedup vs baseline: 1.2483x; 1.2483x over previous
#include <cuda_runtime.h>
#include <cuda_bf16.h>
#include <cstdint>

// Problem constants
#define B_BATCH 64
#define T_LEN   2048
#define F_DIM   256
#define BT      (B_BATCH * T_LEN)   // 131072

// ---------------------------------------------------------------------------
// Scratch (no allocations allowed -> device globals)
// ---------------------------------------------------------------------------
__device__ float g_Wt[F_DIM * F_DIM];   // W, tf32(rna)-rounded, row-major [f][g]
__device__ float g_ait[BT];
__device__ float g_a[BT];
__device__ float g_part[16 * B_BATCH * F_DIM];

__device__ __forceinline__ float to_tf32(float x) {
    float r;
    asm("cvt.rna.tf32.f32 %0, %1;" : "=f"(r) : "f"(x));
    return r;
}

__device__ __forceinline__ uint32_t smem_u32(const void* p) {
    uint32_t a;
    asm("{ .reg .u64 t; cvta.to.shared.u64 t, %1; cvt.u32.u64 %0, t; }" : "=r"(a) : "l"(p));
    return a;
}
__device__ __forceinline__ void cp16(uint32_t dst, const void* src) {
    asm volatile("cp.async.cg.shared.global [%0], [%1], 16;" :: "r"(dst), "l"(src));
}
#define CP_COMMIT()  asm volatile("cp.async.commit_group;" ::: "memory")
#define CP_WAIT(n)   asm volatile("cp.async.wait_group %0;" :: "n"(n) : "memory")

// FMA/ALU-only tanh (no MUFU): tanh(z) = 1 - 2/(1 + e^{2z})
// e^{2z} = 2^t, t = z*2*log2(e); rn-split via float magic; deg-5 poly for 2^f;
// reciprocal via bit-trick seed + 3 Newton iterations. |err| ~ 1e-6.
__device__ __forceinline__ float tanh_fma(float z) {
    z = fminf(fmaxf(z, -9.0f), 9.0f);
    float t = z * 2.885390081777927f;           // 2*log2(e)
    float k = t + 12582912.0f;                  // round-to-nearest int
    int  ki = __float_as_int(k) - 0x4B400000;
    float f = t - (k - 12582912.0f);            // f in [-0.5, 0.5]
    float p = 1.8775767e-3f;
    p = fmaf(p, f, 8.9893397e-3f);
    p = fmaf(p, f, 5.5826318e-2f);
    p = fmaf(p, f, 2.4015361e-1f);
    p = fmaf(p, f, 6.9315308e-1f);
    p = fmaf(p, f, 1.0f);
    float e = __int_as_float(__float_as_int(p) + (ki << 23));   // e^{2z}
    float d = e + 1.0f;
    float r = __int_as_float(0x7EF311C3 - __float_as_int(d));   // ~1/d seed
    r = r * fmaf(-d, r, 2.0f);
    r = r * fmaf(-d, r, 2.0f);
    r = r * fmaf(-d, r, 2.0f);
    return fmaf(-2.0f, r, 1.0f);
}

// ---------------------------------------------------------------------------
// Phase 0: tf32(rna)-round W (once; stays hot in L2)
// ---------------------------------------------------------------------------
__global__ void __launch_bounds__(256) k_wt(const float* __restrict__ W)
{
    int i = blockIdx.x * 256 + threadIdx.x;
    g_Wt[i] = to_tf32(W[i]);
}

// ---------------------------------------------------------------------------
// Phase 1: ait[row] = sum_g tanh((x@W)[row,g] + b[g]) * u[g]
// CTA: 128 rows x 256 cols. 8 warps, grid 2(row)x4(col), warp tile 64x64.
// K streamed in 4 chunks of 64, A+B double-buffered via cp.async.
// mma.sync.m16n8k8.tf32. acc = 128 regs/lane held across k-chunks.
// ---------------------------------------------------------------------------
// smem float offsets
#define A_STRIDE 68            // 68 % 32 == 4 -> A-frag conflict-free
#define B_STRIDE 264           // 264 % 32 == 8 -> B-frag conflict-free
#define A_BUF_FLOATS (128 * A_STRIDE)      // 8704
#define B_BUF_FLOATS (64 * B_STRIDE)       // 16896
#define OFF_A0 0
#define OFF_A1 A_BUF_FLOATS
#define OFF_B0 (2 * A_BUF_FLOATS)                    // 17408
#define OFF_B1 (OFF_B0 + B_BUF_FLOATS)               // 34304
#define OFF_U  (OFF_B0 + 2 * B_BUF_FLOATS)           // 51200
#define OFF_BI (OFF_U + 256)                         // 51456
#define OFF_SR (OFF_BI + 256)                        // 51712
#define SMEM_FLOATS (OFF_SR + 512)                   // 52224
#define SMEM_BYTES  (SMEM_FLOATS * 4)                // 208896

__global__ void __launch_bounds__(256, 1) k_ait(
    const float* __restrict__ x, const float* __restrict__ bias,
    const float* __restrict__ u)
{
    extern __shared__ float smf[];
    const uint32_t smb = smem_u32(smf);
    const int tid  = threadIdx.x;
    const int lane = tid & 31;
    const int wid  = tid >> 5;
    const int q    = lane >> 2;          // groupID (row within frag)
    const int m    = lane & 3;           // threadID-in-group
    const int rg   = wid >> 2;           // row-group 0..1 (64 rows each)
    const int cgr  = wid & 3;            // col-group 0..3 (64 cols each)
    const int mrow = rg * 64;
    const int ncol = cgr * 64;
    const long row0 = (long)blockIdx.x * 128;

    smf[OFF_U  + tid] = u[tid];
    smf[OFF_BI + tid] = bias[tid];

    const float4* xg = reinterpret_cast<const float4*>(x + row0 * F_DIM);

    // Stage chunk c (k = 64c .. 64c+63) into buffer c&1 via cp.async.
    // A: x rows (HW-truncated tf32), B: g_Wt rows (pre-rounded rna).
    auto stage = [&](int c) {
        const int bsel = c & 1;
        const uint32_t abase = smb + (bsel ? OFF_A1 : OFF_A0) * 4;
        const uint32_t bbase = smb + (bsel ? OFF_B1 : OFF_B0) * 4;
        #pragma unroll
        for (int i = 0; i < 8; i++) {            // A: 2048 float4
            int idx = i * 256 + tid;
            int r = idx >> 4, c4 = idx & 15;
            cp16(abase + (r * A_STRIDE + c4 * 4) * 4,
                 xg + r * 64 + c * 16 + c4);
        }
        #pragma unroll
        for (int i = 0; i < 16; i++) {           // B: 4096 float4
            int idx = i * 256 + tid;
            int r = idx >> 6, c4 = idx & 63;
            cp16(bbase + (r * B_STRIDE + c4 * 4) * 4,
                 reinterpret_cast<const float4*>(g_Wt) + (c * 64 + r) * 64 + c4);
        }
        CP_COMMIT();
    };

    float acc[4][8][4];
    #pragma unroll
    for (int mt = 0; mt < 4; mt++)
        #pragma unroll
        for (int nt = 0; nt < 8; nt++)
            #pragma unroll
            for (int i = 0; i < 4; i++) acc[mt][nt][i] = 0.f;

    stage(0);
    stage(1);
    CP_WAIT(1);
    __syncthreads();

    for (int c = 0; c < 4; c++) {
        const int bsel = c & 1;
        const float* xs = smf + (bsel ? OFF_A1 : OFF_A0);
        const float* bs = smf + (bsel ? OFF_B1 : OFF_B0);

        #pragma unroll
        for (int ks = 0; ks < 8; ks++) {
            const int kk0 = ks * 8;
            float a[4][4];
            #pragma unroll
            for (int mt = 0; mt < 4; mt++) {
                const float* ap = xs + (mrow + mt * 16 + q) * A_STRIDE + kk0 + m;
                a[mt][0] = ap[0];
                a[mt][1] = ap[8 * A_STRIDE];
                a[mt][2] = ap[4];
                a[mt][3] = ap[8 * A_STRIDE + 4];
            }
            const float* bp = bs + (kk0 + m) * B_STRIDE + ncol + q;
            float b0[8], b1[8];
            #pragma unroll
            for (int nt = 0; nt < 8; nt++) {
                b0[nt] = bp[nt * 8];
                b1[nt] = bp[4 * B_STRIDE + nt * 8];
            }
            #pragma unroll
            for (int mt = 0; mt < 4; mt++)
                #pragma unroll
                for (int nt = 0; nt < 8; nt++) {
                    asm volatile(
                        "mma.sync.aligned.m16n8k8.row.col.f32.tf32.tf32.f32 "
                        "{%0,%1,%2,%3}, {%4,%5,%6,%7}, {%8,%9}, {%0,%1,%2,%3};"
                        : "+f"(acc[mt][nt][0]), "+f"(acc[mt][nt][1]),
                          "+f"(acc[mt][nt][2]), "+f"(acc[mt][nt][3])
                        : "r"(__float_as_uint(a[mt][0])), "r"(__float_as_uint(a[mt][1])),
                          "r"(__float_as_uint(a[mt][2])), "r"(__float_as_uint(a[mt][3])),
                          "r"(__float_as_uint(b0[nt])), "r"(__float_as_uint(b1[nt])));
                }
        }

        if (c < 2) {
            __syncthreads();          // everyone done reading buf c&1
            stage(c + 2);             // refill it (async)
            CP_WAIT(1);               // chunk c+1 ready
            __syncthreads();
        } else if (c == 2) {
            __syncthreads();
            CP_WAIT(0);               // chunk 3 ready
            __syncthreads();
        }
    }

    // Epilogue: tanh(acc + bias)*u, per-row partials, cross-warp combine.
    const float* usp = smf + OFF_U;
    const float* bip = smf + OFF_BI;
    float* sred = smf + OFF_SR;       // [128][4]
    #pragma unroll
    for (int mt = 0; mt < 4; mt++) {
        float sA = 0.f, sB = 0.f;
        #pragma unroll
        for (int nt = 0; nt < 8; nt++) {
            const int col = ncol + nt * 8 + 2 * m;
            sA = fmaf(tanh_fma(acc[mt][nt][0] + bip[col]),     usp[col],     sA);
            sA = fmaf(tanh_fma(acc[mt][nt][1] + bip[col + 1]), usp[col + 1], sA);
            sB = fmaf(tanh_fma(acc[mt][nt][2] + bip[col]),     usp[col],     sB);
            sB = fmaf(tanh_fma(acc[mt][nt][3] + bip[col + 1]), usp[col + 1], sB);
        }
        sA += __shfl_xor_sync(0xffffffffu, sA, 1);
        sA += __shfl_xor_sync(0xffffffffu, sA, 2);
        sB += __shfl_xor_sync(0xffffffffu, sB, 1);
        sB += __shfl_xor_sync(0xffffffffu, sB, 2);
        if (m == 0) {
            const int r = mrow + mt * 16 + q;
            sred[r * 4 + cgr]       = sA;
            sred[(r + 8) * 4 + cgr] = sB;
        }
    }
    __syncthreads();
    if (tid < 128) {
        const float* s4 = sred + tid * 4;
        g_ait[row0 + tid] = (s4[0] + s4[1]) + (s4[2] + s4[3]);
    }
}

// ---------------------------------------------------------------------------
// Phase 2: a[b,t] = exp(ait)/(sum_t exp(ait) + 1e-7)   (reference: no max-sub)
// ---------------------------------------------------------------------------
__global__ void __launch_bounds__(256) k_softmax()
{
    __shared__ float ex[T_LEN];
    __shared__ float red[256];
    const int b = blockIdx.x, tid = threadIdx.x;
    float s = 0.f;
    for (int i = tid; i < T_LEN; i += 256) {
        float e = expf(g_ait[b * T_LEN + i]);
        ex[i] = e;
        s += e;
    }
    red[tid] = s;
    __syncthreads();
    for (int off = 128; off > 0; off >>= 1) {
        if (tid < off) red[tid] += red[tid + off];
        __syncthreads();
    }
    float inv = 1.f / (red[0] + 1e-7f);
    for (int i = tid; i < T_LEN; i += 256)
        g_a[b * T_LEN + i] = ex[i] * inv;
}

// ---------------------------------------------------------------------------
// Phase 3: partial weighted sums over 128-t chunks (deterministic, no atomics)
// ---------------------------------------------------------------------------
__global__ void __launch_bounds__(256) k_wsum(const float* __restrict__ x)
{
    __shared__ float as[128];
    const int chunk = blockIdx.x, b = blockIdx.y, tid = threadIdx.x;
    const int t0 = chunk * 128;
    if (tid < 128) as[tid] = g_a[b * T_LEN + t0 + tid];
    __syncthreads();
    const float* xb = x + ((long)(b * T_LEN + t0)) * F_DIM + tid;
    float s = 0.f;
    #pragma unroll 8
    for (int tt = 0; tt < 128; tt++)
        s += xb[(long)tt * F_DIM] * as[tt];
    g_part[(chunk * B_BATCH + b) * F_DIM + tid] = s;
}

// ---------------------------------------------------------------------------
// Phase 4: reduce 16 partials -> out[b,f]
// ---------------------------------------------------------------------------
__global__ void __launch_bounds__(256) k_red(float* __restrict__ out)
{
    const int b = blockIdx.x, tid = threadIdx.x;
    float s = 0.f;
    #pragma unroll
    for (int c = 0; c < 16; c++)
        s += g_part[(c * B_BATCH + b) * F_DIM + tid];
    out[b * F_DIM + tid] = s;
}

// ---------------------------------------------------------------------------
extern "C" void kernel_launch(void* const* d_in, const int* in_sizes, int n_in,
                              void* d_out, int out_size)
{
    const float* x    = (const float*)d_in[0];
    const float* W    = (const float*)d_in[1];
    const float* bias = (const float*)d_in[2];
    const float* u    = (const float*)d_in[3];
    float* out = (float*)d_out;

    cudaFuncSetAttribute(k_ait, cudaFuncAttributeMaxDynamicSharedMemorySize, SMEM_BYTES);

    k_wt<<<F_DIM * F_DIM / 256, 256>>>(W);
    k_ait<<<BT / 128, 256, SMEM_BYTES>>>(x, bias, u);
    k_softmax<<<B_BATCH, 256>>>();
    k_wsum<<<dim3(16, B_BATCH), 256>>>(x);
    k_red<<<B_BATCH, 256>>>(out);
}

// round 6
// speedup vs baseline: 1.3333x; 1.0681x over previous
#include <cuda_runtime.h>
#include <cuda_bf16.h>
#include <cstdint>

// Problem constants
#define B_BATCH 64
#define T_LEN   2048
#define F_DIM   256
#define BT      (B_BATCH * T_LEN)   // 131072
#define NBLK    (BT / 128)          // 1024 row-blocks of 128

// ---------------------------------------------------------------------------
// Scratch (no allocations allowed -> device globals)
// ---------------------------------------------------------------------------
__device__ float g_Wt[F_DIM * F_DIM];   // W, tf32(rna)-rounded, row-major [f][g]
__device__ float g_ait[BT];
__device__ float g_sum[B_BATCH];
__device__ float g_part[16 * B_BATCH * F_DIM];

__device__ __forceinline__ float to_tf32(float x) {
    float r;
    asm("cvt.rna.tf32.f32 %0, %1;" : "=f"(r) : "f"(x));
    return r;
}
__device__ __forceinline__ uint32_t smem_u32(const void* p) {
    uint32_t a;
    asm("{ .reg .u64 t; cvta.to.shared.u64 t, %1; cvt.u32.u64 %0, t; }" : "=r"(a) : "l"(p));
    return a;
}
__device__ __forceinline__ void cp16(uint32_t dst, const void* src) {
    asm volatile("cp.async.cg.shared.global [%0], [%1], 16;" :: "r"(dst), "l"(src));
}
#define CP_COMMIT()  asm volatile("cp.async.commit_group;" ::: "memory")
#define CP_WAIT(n)   asm volatile("cp.async.wait_group %0;" :: "n"(n) : "memory")

// ---------------------------------------------------------------------------
// Phase 0: tf32(rna)-round W (once; stays hot in L2)
// ---------------------------------------------------------------------------
__global__ void __launch_bounds__(256) k_wt(const float* __restrict__ W)
{
    int i = blockIdx.x * 256 + threadIdx.x;
    g_Wt[i] = to_tf32(W[i]);
}

// ---------------------------------------------------------------------------
// Phase 1 (persistent): ait[row] = sum_g tanh((x@W)[row,g] + b[g]) * u[g]
// Each CTA owns one SM and loops over row-blocks of 128. Per block:
// K streamed in 4 chunks of 64, A+B double-buffered via cp.async;
// mma.sync.m16n8k8.tf32, 8 warps in 2x4 grid of 64x64 tiles (acc 128 regs).
// Next block's first two chunks are prefetched BEFORE the (MUFU) epilogue.
// ---------------------------------------------------------------------------
#define A_STRIDE 68            // 68 % 32 == 4 -> A-frag conflict-free
#define B_STRIDE 264           // 264 % 32 == 8 -> B-frag conflict-free
#define A_BUF_FLOATS (128 * A_STRIDE)      // 8704
#define B_BUF_FLOATS (64 * B_STRIDE)       // 16896
#define OFF_A0 0
#define OFF_A1 A_BUF_FLOATS
#define OFF_B0 (2 * A_BUF_FLOATS)                    // 17408
#define OFF_B1 (OFF_B0 + B_BUF_FLOATS)               // 34304
#define OFF_U  (OFF_B0 + 2 * B_BUF_FLOATS)           // 51200
#define OFF_BI (OFF_U + 256)                         // 51456
#define OFF_SR (OFF_BI + 256)                        // 51712
#define SMEM_FLOATS (OFF_SR + 512)                   // 52224
#define SMEM_BYTES  (SMEM_FLOATS * 4)                // 208896

__global__ void __launch_bounds__(256, 1) k_ait(
    const float* __restrict__ x, const float* __restrict__ bias,
    const float* __restrict__ u)
{
    extern __shared__ float smf[];
    const uint32_t smb = smem_u32(smf);
    const int tid  = threadIdx.x;
    const int lane = tid & 31;
    const int wid  = tid >> 5;
    const int q    = lane >> 2;          // groupID (row within frag)
    const int m    = lane & 3;           // threadID-in-group
    const int mrow = (wid >> 2) * 64;    // row-group base
    const int cgr  = wid & 3;            // col-group 0..3
    const int ncol = cgr * 64;

    smf[OFF_U  + tid] = u[tid];
    smf[OFF_BI + tid] = bias[tid];

    // Stage chunk c (k = 64c..64c+63) of row-block blk into buffer c&1.
    auto stage = [&](int blk, int c) {
        const float4* xg = reinterpret_cast<const float4*>(x + (long)blk * 128 * F_DIM);
        const int bsel = c & 1;
        const uint32_t abase = smb + (bsel ? OFF_A1 : OFF_A0) * 4;
        const uint32_t bbase = smb + (bsel ? OFF_B1 : OFF_B0) * 4;
        #pragma unroll
        for (int i = 0; i < 8; i++) {            // A: 2048 float4
            int idx = i * 256 + tid;
            int r = idx >> 4, c4 = idx & 15;
            cp16(abase + (r * A_STRIDE + c4 * 4) * 4,
                 xg + r * 64 + c * 16 + c4);
        }
        #pragma unroll
        for (int i = 0; i < 16; i++) {           // B: 4096 float4
            int idx = i * 256 + tid;
            int r = idx >> 6, c4 = idx & 63;
            cp16(bbase + (r * B_STRIDE + c4 * 4) * 4,
                 reinterpret_cast<const float4*>(g_Wt) + (c * 64 + r) * 64 + c4);
        }
        CP_COMMIT();
    };

    int blk = blockIdx.x;
    stage(blk, 0);
    stage(blk, 1);

    for (; blk < NBLK; blk += gridDim.x) {
        float acc[4][8][4];
        #pragma unroll
        for (int mt = 0; mt < 4; mt++)
            #pragma unroll
            for (int nt = 0; nt < 8; nt++)
                #pragma unroll
                for (int i = 0; i < 4; i++) acc[mt][nt][i] = 0.f;

        for (int c = 0; c < 4; c++) {
            if (c == 0) { CP_WAIT(1); __syncthreads(); }
            const int bsel = c & 1;
            const float* xs = smf + (bsel ? OFF_A1 : OFF_A0);
            const float* bs = smf + (bsel ? OFF_B1 : OFF_B0);

            #pragma unroll
            for (int ks = 0; ks < 8; ks++) {
                const int kk0 = ks * 8;
                float a[4][4];
                #pragma unroll
                for (int mt = 0; mt < 4; mt++) {
                    const float* ap = xs + (mrow + mt * 16 + q) * A_STRIDE + kk0 + m;
                    a[mt][0] = ap[0];
                    a[mt][1] = ap[8 * A_STRIDE];
                    a[mt][2] = ap[4];
                    a[mt][3] = ap[8 * A_STRIDE + 4];
                }
                const float* bp = bs + (kk0 + m) * B_STRIDE + ncol + q;
                float b0[8], b1[8];
                #pragma unroll
                for (int nt = 0; nt < 8; nt++) {
                    b0[nt] = bp[nt * 8];
                    b1[nt] = bp[4 * B_STRIDE + nt * 8];
                }
                #pragma unroll
                for (int mt = 0; mt < 4; mt++)
                    #pragma unroll
                    for (int nt = 0; nt < 8; nt++) {
                        asm volatile(
                            "mma.sync.aligned.m16n8k8.row.col.f32.tf32.tf32.f32 "
                            "{%0,%1,%2,%3}, {%4,%5,%6,%7}, {%8,%9}, {%0,%1,%2,%3};"
                            : "+f"(acc[mt][nt][0]), "+f"(acc[mt][nt][1]),
                              "+f"(acc[mt][nt][2]), "+f"(acc[mt][nt][3])
                            : "r"(__float_as_uint(a[mt][0])), "r"(__float_as_uint(a[mt][1])),
                              "r"(__float_as_uint(a[mt][2])), "r"(__float_as_uint(a[mt][3])),
                              "r"(__float_as_uint(b0[nt])), "r"(__float_as_uint(b1[nt])));
                    }
            }

            if (c < 2) {
                __syncthreads();          // all warps done reading buf c&1
                stage(blk, c + 2);        // refill it (async)
                CP_WAIT(1);               // chunk c+1 ready
                __syncthreads();
            } else if (c == 2) {
                __syncthreads();
                CP_WAIT(0);               // chunk 3 ready
                __syncthreads();
            }
        }

        // All buffers free: prefetch next block's first two chunks so the
        // epilogue below overlaps the memory fetch.
        __syncthreads();
        const int nblk = blk + gridDim.x;
        if (nblk < NBLK) {
            stage(nblk, 0);
            stage(nblk, 1);
        }

        // Epilogue: tanh(acc + bias)*u via MUFU (EX2 + RCP), per-row partials.
        const float* usp = smf + OFF_U;
        const float* bip = smf + OFF_BI;
        float* sred = smf + OFF_SR;       // [128][4]
        #pragma unroll
        for (int mt = 0; mt < 4; mt++) {
            float sA = 0.f, sB = 0.f;
            #pragma unroll
            for (int nt = 0; nt < 8; nt++) {
                const int col = ncol + nt * 8 + 2 * m;
                #pragma unroll
                for (int h = 0; h < 2; h++) {
                    float z0 = acc[mt][nt][h]     + bip[col + h];
                    float z1 = acc[mt][nt][h + 2] + bip[col + h];
                    z0 = fminf(fmaxf(z0, -15.f), 15.f);
                    z1 = fminf(fmaxf(z1, -15.f), 15.f);
                    const float e0 = __expf(2.f * z0);
                    const float e1 = __expf(2.f * z1);
                    sA = fmaf(__fdividef(e0 - 1.f, e0 + 1.f), usp[col + h], sA);
                    sB = fmaf(__fdividef(e1 - 1.f, e1 + 1.f), usp[col + h], sB);
                }
            }
            sA += __shfl_xor_sync(0xffffffffu, sA, 1);
            sA += __shfl_xor_sync(0xffffffffu, sA, 2);
            sB += __shfl_xor_sync(0xffffffffu, sB, 1);
            sB += __shfl_xor_sync(0xffffffffu, sB, 2);
            if (m == 0) {
                const int r = mrow + mt * 16 + q;
                sred[r * 4 + cgr]       = sA;
                sred[(r + 8) * 4 + cgr] = sB;
            }
        }
        __syncthreads();
        if (tid < 128) {
            const float* s4 = sred + tid * 4;
            g_ait[(long)blk * 128 + tid] = (s4[0] + s4[1]) + (s4[2] + s4[3]);
        }
    }
}

// ---------------------------------------------------------------------------
// Phase 2: g_sum[b] = sum_t exp(ait[b,t])
// ---------------------------------------------------------------------------
__global__ void __launch_bounds__(256) k_softsum()
{
    __shared__ float red[256];
    const int b = blockIdx.x, tid = threadIdx.x;
    float s = 0.f;
    for (int i = tid; i < T_LEN; i += 256)
        s += expf(g_ait[b * T_LEN + i]);
    red[tid] = s;
    __syncthreads();
    for (int off = 128; off > 0; off >>= 1) {
        if (tid < off) red[tid] += red[tid + off];
        __syncthreads();
    }
    if (tid == 0) g_sum[b] = red[0];
}

// ---------------------------------------------------------------------------
// Phase 3: partial weighted sums over 128-t chunks (float4, deterministic)
// a[b,t] = exp(ait)/(sum+eps) recomputed locally (each (b,t) in exactly 1 CTA)
// ---------------------------------------------------------------------------
__global__ void __launch_bounds__(256) k_wsum(const float* __restrict__ x)
{
    __shared__ float  as[128];
    __shared__ float4 sp[256];
    const int chunk = blockIdx.x, b = blockIdx.y, tid = threadIdx.x;
    const int t0 = chunk * 128;
    const float inv = 1.f / (g_sum[b] + 1e-7f);
    if (tid < 128)
        as[tid] = expf(g_ait[b * T_LEN + t0 + tid]) * inv;
    __syncthreads();

    const int f4 = tid & 63, ts = tid >> 6;
    const float4* xb = reinterpret_cast<const float4*>(
        x + ((long)(b * T_LEN + t0)) * F_DIM);
    float4 acc = make_float4(0.f, 0.f, 0.f, 0.f);
    #pragma unroll 8
    for (int tt = ts; tt < 128; tt += 4) {
        const float4 v = xb[tt * 64 + f4];
        const float  a = as[tt];
        acc.x = fmaf(v.x, a, acc.x);
        acc.y = fmaf(v.y, a, acc.y);
        acc.z = fmaf(v.z, a, acc.z);
        acc.w = fmaf(v.w, a, acc.w);
    }
    sp[ts * 64 + f4] = acc;
    __syncthreads();
    if (ts == 0) {
        const float4 a0 = sp[f4], a1 = sp[64 + f4], a2 = sp[128 + f4], a3 = sp[192 + f4];
        float4 r;
        r.x = (a0.x + a1.x) + (a2.x + a3.x);
        r.y = (a0.y + a1.y) + (a2.y + a3.y);
        r.z = (a0.z + a1.z) + (a2.z + a3.z);
        r.w = (a0.w + a1.w) + (a2.w + a3.w);
        reinterpret_cast<float4*>(g_part + (chunk * B_BATCH + b) * F_DIM)[f4] = r;
    }
}

// ---------------------------------------------------------------------------
// Phase 4: reduce 16 partials -> out[b,f] (float4)
// ---------------------------------------------------------------------------
__global__ void __launch_bounds__(64) k_red(float* __restrict__ out)
{
    const int b = blockIdx.x, tid = threadIdx.x;
    const float4* gp = reinterpret_cast<const float4*>(g_part);
    float4 s = make_float4(0.f, 0.f, 0.f, 0.f);
    #pragma unroll
    for (int c = 0; c < 16; c++) {
        const float4 v = gp[(c * B_BATCH + b) * 64 + tid];
        s.x += v.x; s.y += v.y; s.z += v.z; s.w += v.w;
    }
    reinterpret_cast<float4*>(out)[b * 64 + tid] = s;
}

// ---------------------------------------------------------------------------
extern "C" void kernel_launch(void* const* d_in, const int* in_sizes, int n_in,
                              void* d_out, int out_size)
{
    const float* x    = (const float*)d_in[0];
    const float* W    = (const float*)d_in[1];
    const float* bias = (const float*)d_in[2];
    const float* u    = (const float*)d_in[3];
    float* out = (float*)d_out;

    cudaFuncSetAttribute(k_ait, cudaFuncAttributeMaxDynamicSharedMemorySize, SMEM_BYTES);

    k_wt<<<F_DIM * F_DIM / 256, 256>>>(W);
    k_ait<<<152, 256, SMEM_BYTES>>>(x, bias, u);   // persistent: 1 CTA per SM
    k_softsum<<<B_BATCH, 256>>>();
    k_wsum<<<dim3(16, B_BATCH), 256>>>(x);
    k_red<<<B_BATCH, 64>>>(out);
}

// round 7
// speedup vs baseline: 1.3342x; 1.0007x over previous
#include <cuda_runtime.h>
#include <cuda_bf16.h>
#include <cstdint>

// Problem constants
#define B_BATCH 64
#define T_LEN   2048
#define F_DIM   256
#define BT      (B_BATCH * T_LEN)   // 131072
#define NSB     (BT / 256)          // 512 super-blocks of 256 rows
#define NCTA    152                 // GB300: 152 SMs, persistent 1 CTA/SM
#define HSTEP   (NCTA / 2)          // 76 CTAs per N-half

// ---------------------------------------------------------------------------
// Scratch (no allocations allowed -> device globals)
// ---------------------------------------------------------------------------
__device__ float g_Wt[F_DIM * F_DIM];   // W, tf32(rna)-rounded, row-major [f][g]
__device__ float g_aitp[2][BT];         // per-half partial ait
__device__ float g_sum[B_BATCH];
__device__ float g_part[16 * B_BATCH * F_DIM];

__device__ __forceinline__ float to_tf32(float x) {
    float r;
    asm("cvt.rna.tf32.f32 %0, %1;" : "=f"(r) : "f"(x));
    return r;
}
__device__ __forceinline__ uint32_t smem_u32(const void* p) {
    uint32_t a;
    asm("{ .reg .u64 t; cvta.to.shared.u64 t, %1; cvt.u32.u64 %0, t; }" : "=r"(a) : "l"(p));
    return a;
}
__device__ __forceinline__ void cp16(uint32_t dst, const void* src) {
    asm volatile("cp.async.cg.shared.global [%0], [%1], 16;" :: "r"(dst), "l"(src));
}
#define CP_COMMIT()  asm volatile("cp.async.commit_group;" ::: "memory")
#define CP_WAIT(n)   asm volatile("cp.async.wait_group %0;" :: "n"(n) : "memory")

// ---------------------------------------------------------------------------
// Phase 0: tf32(rna)-round W (once; stays hot in L2)
// ---------------------------------------------------------------------------
__global__ void __launch_bounds__(256) k_wt(const float* __restrict__ W)
{
    int i = blockIdx.x * 256 + threadIdx.x;
    g_Wt[i] = to_tf32(W[i]);
}

// ---------------------------------------------------------------------------
// Phase 1 (persistent, N-split): partial ait over a fixed 128-col half.
//   CTA h = blockIdx.x & 1 owns cols [128h, 128h+128).
//   B half (256k x 128n, stride 136) resident in smem, loaded ONCE.
//   A streamed per super-block (256 rows) in 8 double-buffered k=32 chunks.
//   8 warps: 4(row) x 2(col) grid of 64x64 tiles; mma.sync m16n8k8 tf32.
// ---------------------------------------------------------------------------
#define A_STRIDE 36             // 36 % 32 == 4 -> A-frag banks 4q+m distinct
#define B_STRIDE 136            // 136 % 32 == 8 -> B-frag banks 8m+q distinct
#define A_BUF_FLOATS (256 * A_STRIDE)      // 9216
#define OFF_A0 0
#define OFF_A1 A_BUF_FLOATS                          // 9216
#define OFF_B  (2 * A_BUF_FLOATS)                    // 18432
#define B_FLOATS (256 * B_STRIDE)                    // 34816
#define OFF_U  (OFF_B + B_FLOATS)                    // 53248
#define OFF_BI (OFF_U + 128)                         // 53376
#define OFF_SR (OFF_BI + 128)                        // 53504
#define SMEM_FLOATS (OFF_SR + 512)                   // 54016
#define SMEM_BYTES  (SMEM_FLOATS * 4)                // 216064

__global__ void __launch_bounds__(256, 1) k_ait(
    const float* __restrict__ x, const float* __restrict__ bias,
    const float* __restrict__ u)
{
    extern __shared__ float smf[];
    const uint32_t smb = smem_u32(smf);
    const int tid  = threadIdx.x;
    const int lane = tid & 31;
    const int wid  = tid >> 5;
    const int q    = lane >> 2;          // groupID (row within frag)
    const int m    = lane & 3;           // threadID-in-group
    const int mrow = (wid >> 1) * 64;    // row-group base (0..192)
    const int cg   = wid & 1;            // col-group 0..1
    const int ncol = cg * 64;
    const int h    = blockIdx.x & 1;     // N-half

    if (tid < 128) {
        smf[OFF_U  + tid] = u[h * 128 + tid];
        smf[OFF_BI + tid] = bias[h * 128 + tid];
    }

    // Load resident B half: g_Wt[k][128h..128h+127] -> [k][n] stride 136.
    {
        const float4* wg = reinterpret_cast<const float4*>(g_Wt);
        #pragma unroll
        for (int i = 0; i < 32; i++) {           // 8192 float4
            int idx = i * 256 + tid;
            int k = idx >> 5, c4 = idx & 31;     // 32 float4 per 128-col row
            cp16(smb + (OFF_B + k * B_STRIDE + c4 * 4) * 4,
                 wg + k * 64 + h * 32 + c4);
        }
        CP_COMMIT();
    }

    // Stage A chunk c (k = 32c..32c+31) of super-block sb into buffer c&1.
    auto stageA = [&](int sb, int c) {
        const float4* xg = reinterpret_cast<const float4*>(x + (long)sb * 256 * F_DIM);
        const uint32_t abase = smb + ((c & 1) ? OFF_A1 : OFF_A0) * 4;
        #pragma unroll
        for (int i = 0; i < 8; i++) {            // 2048 float4
            int idx = i * 256 + tid;
            int r = idx >> 3, c4 = idx & 7;      // 8 float4 per 32-k row
            cp16(abase + (r * A_STRIDE + c4 * 4) * 4,
                 xg + r * 64 + c * 8 + c4);
        }
        CP_COMMIT();
    };

    int sb = blockIdx.x >> 1;
    stageA(sb, 0);
    stageA(sb, 1);

    for (; sb < NSB; sb += HSTEP) {
        float acc[4][8][4];
        #pragma unroll
        for (int mt = 0; mt < 4; mt++)
            #pragma unroll
            for (int nt = 0; nt < 8; nt++)
                #pragma unroll
                for (int i = 0; i < 4; i++) acc[mt][nt][i] = 0.f;

        for (int c = 0; c < 8; c++) {
            if (c == 0) { CP_WAIT(1); __syncthreads(); }   // chunk0 (+B) ready
            const float* xs = smf + ((c & 1) ? OFF_A1 : OFF_A0);
            const float* bsb = smf + OFF_B + c * 32 * B_STRIDE;

            #pragma unroll
            for (int ks = 0; ks < 4; ks++) {
                const int kk0 = ks * 8;
                float a[4][4];
                #pragma unroll
                for (int mt = 0; mt < 4; mt++) {
                    const float* ap = xs + (mrow + mt * 16 + q) * A_STRIDE + kk0 + m;
                    a[mt][0] = ap[0];
                    a[mt][1] = ap[8 * A_STRIDE];
                    a[mt][2] = ap[4];
                    a[mt][3] = ap[8 * A_STRIDE + 4];
                }
                const float* bp = bsb + (kk0 + m) * B_STRIDE + ncol + q;
                float b0[8], b1[8];
                #pragma unroll
                for (int nt = 0; nt < 8; nt++) {
                    b0[nt] = bp[nt * 8];
                    b1[nt] = bp[4 * B_STRIDE + nt * 8];
                }
                #pragma unroll
                for (int mt = 0; mt < 4; mt++)
                    #pragma unroll
                    for (int nt = 0; nt < 8; nt++) {
                        asm volatile(
                            "mma.sync.aligned.m16n8k8.row.col.f32.tf32.tf32.f32 "
                            "{%0,%1,%2,%3}, {%4,%5,%6,%7}, {%8,%9}, {%0,%1,%2,%3};"
                            : "+f"(acc[mt][nt][0]), "+f"(acc[mt][nt][1]),
                              "+f"(acc[mt][nt][2]), "+f"(acc[mt][nt][3])
                            : "r"(__float_as_uint(a[mt][0])), "r"(__float_as_uint(a[mt][1])),
                              "r"(__float_as_uint(a[mt][2])), "r"(__float_as_uint(a[mt][3])),
                              "r"(__float_as_uint(b0[nt])), "r"(__float_as_uint(b1[nt])));
                    }
            }

            if (c < 6) {
                __syncthreads();          // all warps done reading buf c&1
                stageA(sb, c + 2);        // refill it (async)
                CP_WAIT(1);               // chunk c+1 ready
                __syncthreads();
            } else if (c == 6) {
                __syncthreads();
                CP_WAIT(0);               // chunk 7 ready
                __syncthreads();
            }
        }

        // Buffers free: prefetch next super-block's first two chunks so the
        // epilogue overlaps the fetch.
        __syncthreads();
        const int nsb = sb + HSTEP;
        if (nsb < NSB) {
            stageA(nsb, 0);
            stageA(nsb, 1);
        }

        // Epilogue: tanh(acc + bias)*u via MUFU, per-row partial over 128 cols.
        const float* usp = smf + OFF_U;
        const float* bip = smf + OFF_BI;
        float* sred = smf + OFF_SR;       // [256][2]
        #pragma unroll
        for (int mt = 0; mt < 4; mt++) {
            float sA = 0.f, sB = 0.f;
            #pragma unroll
            for (int nt = 0; nt < 8; nt++) {
                const int col = ncol + nt * 8 + 2 * m;
                #pragma unroll
                for (int hh = 0; hh < 2; hh++) {
                    float z0 = acc[mt][nt][hh]     + bip[col + hh];
                    float z1 = acc[mt][nt][hh + 2] + bip[col + hh];
                    z0 = fminf(fmaxf(z0, -15.f), 15.f);
                    z1 = fminf(fmaxf(z1, -15.f), 15.f);
                    const float e0 = __expf(2.f * z0);
                    const float e1 = __expf(2.f * z1);
                    sA = fmaf(__fdividef(e0 - 1.f, e0 + 1.f), usp[col + hh], sA);
                    sB = fmaf(__fdividef(e1 - 1.f, e1 + 1.f), usp[col + hh], sB);
                }
            }
            sA += __shfl_xor_sync(0xffffffffu, sA, 1);
            sA += __shfl_xor_sync(0xffffffffu, sA, 2);
            sB += __shfl_xor_sync(0xffffffffu, sB, 1);
            sB += __shfl_xor_sync(0xffffffffu, sB, 2);
            if (m == 0) {
                const int r = mrow + mt * 16 + q;
                sred[r * 2 + cg]       = sA;
                sred[(r + 8) * 2 + cg] = sB;
            }
        }
        __syncthreads();
        g_aitp[h][(long)sb * 256 + tid] = sred[tid * 2] + sred[tid * 2 + 1];
    }
}

// ---------------------------------------------------------------------------
// Phase 2: g_sum[b] = sum_t exp(ait[b,t]),  ait = p0 + p1
// ---------------------------------------------------------------------------
__global__ void __launch_bounds__(256) k_softsum()
{
    __shared__ float red[256];
    const int b = blockIdx.x, tid = threadIdx.x;
    float s = 0.f;
    for (int i = tid; i < T_LEN; i += 256) {
        const int r = b * T_LEN + i;
        s += expf(g_aitp[0][r] + g_aitp[1][r]);
    }
    red[tid] = s;
    __syncthreads();
    for (int off = 128; off > 0; off >>= 1) {
        if (tid < off) red[tid] += red[tid + off];
        __syncthreads();
    }
    if (tid == 0) g_sum[b] = red[0];
}

// ---------------------------------------------------------------------------
// Phase 3: partial weighted sums over 128-t chunks (float4, deterministic)
// ---------------------------------------------------------------------------
__global__ void __launch_bounds__(256) k_wsum(const float* __restrict__ x)
{
    __shared__ float  as[128];
    __shared__ float4 sp[256];
    const int chunk = blockIdx.x, b = blockIdx.y, tid = threadIdx.x;
    const int t0 = chunk * 128;
    const float inv = 1.f / (g_sum[b] + 1e-7f);
    if (tid < 128) {
        const int r = b * T_LEN + t0 + tid;
        as[tid] = expf(g_aitp[0][r] + g_aitp[1][r]) * inv;
    }
    __syncthreads();

    const int f4 = tid & 63, ts = tid >> 6;
    const float4* xb = reinterpret_cast<const float4*>(
        x + ((long)(b * T_LEN + t0)) * F_DIM);
    float4 acc = make_float4(0.f, 0.f, 0.f, 0.f);
    #pragma unroll 8
    for (int tt = ts; tt < 128; tt += 4) {
        const float4 v = xb[tt * 64 + f4];
        const float  a = as[tt];
        acc.x = fmaf(v.x, a, acc.x);
        acc.y = fmaf(v.y, a, acc.y);
        acc.z = fmaf(v.z, a, acc.z);
        acc.w = fmaf(v.w, a, acc.w);
    }
    sp[ts * 64 + f4] = acc;
    __syncthreads();
    if (ts == 0) {
        const float4 a0 = sp[f4], a1 = sp[64 + f4], a2 = sp[128 + f4], a3 = sp[192 + f4];
        float4 r;
        r.x = (a0.x + a1.x) + (a2.x + a3.x);
        r.y = (a0.y + a1.y) + (a2.y + a3.y);
        r.z = (a0.z + a1.z) + (a2.z + a3.z);
        r.w = (a0.w + a1.w) + (a2.w + a3.w);
        reinterpret_cast<float4*>(g_part + (chunk * B_BATCH + b) * F_DIM)[f4] = r;
    }
}

// ---------------------------------------------------------------------------
// Phase 4: reduce 16 partials -> out[b,f] (float4)
// ---------------------------------------------------------------------------
__global__ void __launch_bounds__(64) k_red(float* __restrict__ out)
{
    const int b = blockIdx.x, tid = threadIdx.x;
    const float4* gp = reinterpret_cast<const float4*>(g_part);
    float4 s = make_float4(0.f, 0.f, 0.f, 0.f);
    #pragma unroll
    for (int c = 0; c < 16; c++) {
        const float4 v = gp[(c * B_BATCH + b) * 64 + tid];
        s.x += v.x; s.y += v.y; s.z += v.z; s.w += v.w;
    }
    reinterpret_cast<float4*>(out)[b * 64 + tid] = s;
}

// ---------------------------------------------------------------------------
extern "C" void kernel_launch(void* const* d_in, const int* in_sizes, int n_in,
                              void* d_out, int out_size)
{
    const float* x    = (const float*)d_in[0];
    const float* W    = (const float*)d_in[1];
    const float* bias = (const float*)d_in[2];
    const float* u    = (const float*)d_in[3];
    float* out = (float*)d_out;

    cudaFuncSetAttribute(k_ait, cudaFuncAttributeMaxDynamicSharedMemorySize, SMEM_BYTES);

    k_wt<<<F_DIM * F_DIM / 256, 256>>>(W);
    k_ait<<<NCTA, 256, SMEM_BYTES>>>(x, bias, u);   // persistent, N-split halves
    k_softsum<<<B_BATCH, 256>>>();
    k_wsum<<<dim3(16, B_BATCH), 256>>>(x);
    k_red<<<B_BATCH, 64>>>(out);
}

// round 9
// speedup vs baseline: 1.6211x; 1.2150x over previous
#include <cuda_runtime.h>
#include <cuda_fp16.h>
#include <cuda_bf16.h>
#include <cstdint>

// Problem constants
#define B_BATCH 64
#define T_LEN   2048
#define F_DIM   256
#define BT      (B_BATCH * T_LEN)   // 131072
#define NSB     (BT / 256)          // 512 super-blocks of 256 rows
#define NCTA    152                 // GB300: 152 SMs, persistent 1 CTA/SM
#define HSTEP   (NCTA / 2)          // 76 CTAs per N-half

// ---------------------------------------------------------------------------
// Scratch (no allocations allowed -> device globals)
// ---------------------------------------------------------------------------
__device__ __half g_Wh[F_DIM * F_DIM]; // W^T in fp16: g_Wh[g*256+f] = W[f][g]
__device__ float g_aitp[2][BT];        // per-half partial ait
__device__ float g_sum[B_BATCH];
__device__ float g_part[16 * B_BATCH * F_DIM];

__device__ __forceinline__ uint32_t smem_u32(const void* p) {
    uint32_t a;
    asm("{ .reg .u64 t; cvta.to.shared.u64 t, %1; cvt.u32.u64 %0, t; }" : "=r"(a) : "l"(p));
    return a;
}
__device__ __forceinline__ void cp16(uint32_t dst, const void* src) {
    asm volatile("cp.async.cg.shared.global [%0], [%1], 16;" :: "r"(dst), "l"(src));
}
#define CP_COMMIT()  asm volatile("cp.async.commit_group;" ::: "memory")
#define CP_WAIT(n)   asm volatile("cp.async.wait_group %0;" :: "n"(n) : "memory")

// ---------------------------------------------------------------------------
// Phase 0: W -> fp16, transposed to [g][f] (K-major for the B operand)
// ---------------------------------------------------------------------------
__global__ void __launch_bounds__(256) k_wt(const float* __restrict__ W)
{
    __shared__ float tile[32][33];
    const int tx = threadIdx.x, ty = threadIdx.y;
    const int gx = blockIdx.x * 32, gy = blockIdx.y * 32;
    #pragma unroll
    for (int j = ty; j < 32; j += 8)
        tile[j][tx] = W[(gy + j) * F_DIM + gx + tx];
    __syncthreads();
    #pragma unroll
    for (int j = ty; j < 32; j += 8)
        g_Wh[(gx + j) * F_DIM + gy + tx] = __float2half_rn(tile[tx][j]);
}

// ---------------------------------------------------------------------------
// Phase 1 (persistent, N-split, fp16 mma): partial ait over a 128-col half.
//   CTA h = blockIdx.x & 1 owns cols [128h, 128h+128).
//   B half (fp16, [n][k], word-stride 132) resident in smem, loaded once.
//   A streamed per super-block (256 rows) in 8 double-buffered k=32 chunks:
//   LDG float4 (prefetched one chunk ahead) -> cvt fp16 -> STS.
//   8 warps: 4(row) x 2(col) grid of 64x64 tiles; mma.sync m16n8k16 f16.f32.
// ---------------------------------------------------------------------------
#define SA_W 20                 // A row stride, 32-bit words (20 mod 8 == 4: 20q+m distinct)
#define SB_W 132                // B row stride, words (132 mod 8 == 4: 4q+m distinct)
#define A_BUF_W (256 * SA_W)    // 5120 words
#define OFF_A0 0
#define OFF_A1 A_BUF_W                        // 5120
#define OFF_B  (2 * A_BUF_W)                  // 10240
#define B_WORDS (128 * SB_W)                  // 16896
#define OFF_U  (OFF_B + B_WORDS)              // 27136 (floats)
#define OFF_BI (OFF_U + 128)                  // 27264
#define OFF_SR (OFF_BI + 128)                 // 27392
#define SMEM_WORDS (OFF_SR + 512)             // 27904
#define SMEM_BYTES (SMEM_WORDS * 4)           // 111,616

__global__ void __launch_bounds__(256, 1) k_ait(
    const float* __restrict__ x, const float* __restrict__ bias,
    const float* __restrict__ u)
{
    extern __shared__ uint32_t smw[];
    const uint32_t smb = smem_u32(smw);
    const int tid  = threadIdx.x;
    const int lane = tid & 31;
    const int wid  = tid >> 5;
    const int q    = lane >> 2;          // groupID (row within frag)
    const int m    = lane & 3;           // threadID-in-group
    const int mrow = (wid >> 1) * 64;    // row-group base (0..192)
    const int cg   = wid & 1;            // col-group 0..1
    const int ncol = cg * 64;
    const int h    = blockIdx.x & 1;     // N-half

    float* usp = reinterpret_cast<float*>(smw + OFF_U);
    float* bip = reinterpret_cast<float*>(smw + OFF_BI);
    if (tid < 128) {
        usp[tid] = u[h * 128 + tid];
        bip[tid] = bias[h * 128 + tid];
    }

    // Resident B half via cp.async: g_Wh rows n = 128h..128h+127, 256 halfs.
    {
        #pragma unroll
        for (int i = 0; i < 16; i++) {           // 4096 x 16B
            int idx = i * 256 + tid;
            int n = idx >> 5, c16 = idx & 31;    // 32 x 16B per row
            cp16(smb + (OFF_B + n * SB_W + c16 * 4) * 4,
                 g_Wh + (h * 128 + n) * F_DIM + c16 * 8);
        }
        CP_COMMIT();
    }

    const float4* xg4 = reinterpret_cast<const float4*>(x);

    // LDG chunk c (k = 32c..32c+31) of super-block sb into registers.
    auto ldgA = [&](int sb_, int c_, float4* R) {
        const float4* xg = xg4 + (long)sb_ * 256 * 64;
        #pragma unroll
        for (int i = 0; i < 8; i++) {
            int idx = i * 256 + tid;
            int r = idx >> 3, c4 = idx & 7;      // 8 float4 per 32-k row
            R[i] = __ldg(xg + r * 64 + c_ * 8 + c4);
        }
    };
    // Convert + store registers into A buffer bsel.
    auto stsA = [&](const float4* R, int bsel) {
        uint32_t* ab = smw + (bsel ? OFF_A1 : OFF_A0);
        #pragma unroll
        for (int i = 0; i < 8; i++) {
            int idx = i * 256 + tid;
            int r = idx >> 3, c4 = idx & 7;
            __half2 h0 = __floats2half2_rn(R[i].x, R[i].y);
            __half2 h1 = __floats2half2_rn(R[i].z, R[i].w);
            uint2 v;
            v.x = *reinterpret_cast<uint32_t*>(&h0);
            v.y = *reinterpret_cast<uint32_t*>(&h1);
            *reinterpret_cast<uint2*>(ab + r * SA_W + c4 * 2) = v;
        }
    };

    int sb = blockIdx.x >> 1;
    float4 R[8];
    ldgA(sb, 0, R);
    CP_WAIT(0);                  // B resident ready

    for (; sb < NSB; sb += HSTEP) {
        stsA(R, 0);
        __syncthreads();
        ldgA(sb, 1, R);

        float acc[4][8][4];
        #pragma unroll
        for (int mt = 0; mt < 4; mt++)
            #pragma unroll
            for (int nt = 0; nt < 8; nt++)
                #pragma unroll
                for (int i = 0; i < 4; i++) acc[mt][nt][i] = 0.f;

        for (int c = 0; c < 8; c++) {
            const uint32_t* ab = smw + ((c & 1) ? OFF_A1 : OFF_A0);
            const uint32_t* bb = smw + OFF_B;

            #pragma unroll
            for (int s = 0; s < 2; s++) {        // two k16 steps per chunk
                const int kb = 8 * s;            // word offset within chunk
                uint32_t a[4][4];
                #pragma unroll
                for (int mt = 0; mt < 4; mt++) {
                    const uint32_t* ap = ab + (mrow + mt * 16 + q) * SA_W + kb + m;
                    a[mt][0] = ap[0];
                    a[mt][1] = ap[8 * SA_W];
                    a[mt][2] = ap[4];
                    a[mt][3] = ap[8 * SA_W + 4];
                }
                const uint32_t* bp = bb + (ncol + q) * SB_W + 16 * c + kb + m;
                uint32_t b0[8], b1[8];
                #pragma unroll
                for (int nt = 0; nt < 8; nt++) {
                    b0[nt] = bp[nt * 8 * SB_W];
                    b1[nt] = bp[nt * 8 * SB_W + 4];
                }
                #pragma unroll
                for (int mt = 0; mt < 4; mt++)
                    #pragma unroll
                    for (int nt = 0; nt < 8; nt++) {
                        asm volatile(
                            "mma.sync.aligned.m16n8k16.row.col.f32.f16.f16.f32 "
                            "{%0,%1,%2,%3}, {%4,%5,%6,%7}, {%8,%9}, {%0,%1,%2,%3};"
                            : "+f"(acc[mt][nt][0]), "+f"(acc[mt][nt][1]),
                              "+f"(acc[mt][nt][2]), "+f"(acc[mt][nt][3])
                            : "r"(a[mt][0]), "r"(a[mt][1]),
                              "r"(a[mt][2]), "r"(a[mt][3]),
                              "r"(b0[nt]), "r"(b1[nt]));
                    }
            }

            __syncthreads();
            if (c < 7) {
                stsA(R, (c + 1) & 1);            // chunk c+1 into its buffer
                int nsb2 = sb, nc = c + 2;       // prefetch chunk c+2 (or next sb's 0)
                if (nc > 7) { nsb2 = min(sb + HSTEP, NSB - 1); nc = 0; }
                ldgA(nsb2, nc, R);
                __syncthreads();
            }
        }
        // R now holds chunk 0 of the next super-block (LDG issued at c==6).

        // Epilogue: tanh(acc + bias)*u via MUFU, per-row partial over 128 cols.
        float* sred = reinterpret_cast<float*>(smw + OFF_SR);   // [256][2]
        #pragma unroll
        for (int mt = 0; mt < 4; mt++) {
            float sA = 0.f, sB = 0.f;
            #pragma unroll
            for (int nt = 0; nt < 8; nt++) {
                const int col = ncol + nt * 8 + 2 * m;
                #pragma unroll
                for (int hh = 0; hh < 2; hh++) {
                    float z0 = acc[mt][nt][hh]     + bip[col + hh];
                    float z1 = acc[mt][nt][hh + 2] + bip[col + hh];
                    z0 = fminf(fmaxf(z0, -15.f), 15.f);
                    z1 = fminf(fmaxf(z1, -15.f), 15.f);
                    const float e0 = __expf(2.f * z0);
                    const float e1 = __expf(2.f * z1);
                    sA = fmaf(__fdividef(e0 - 1.f, e0 + 1.f), usp[col + hh], sA);
                    sB = fmaf(__fdividef(e1 - 1.f, e1 + 1.f), usp[col + hh], sB);
                }
            }
            sA += __shfl_xor_sync(0xffffffffu, sA, 1);
            sA += __shfl_xor_sync(0xffffffffu, sA, 2);
            sB += __shfl_xor_sync(0xffffffffu, sB, 1);
            sB += __shfl_xor_sync(0xffffffffu, sB, 2);
            if (m == 0) {
                const int r = mrow + mt * 16 + q;
                sred[r * 2 + cg]       = sA;
                sred[(r + 8) * 2 + cg] = sB;
            }
        }
        __syncthreads();
        g_aitp[h][(long)sb * 256 + tid] = sred[tid * 2] + sred[tid * 2 + 1];
        __syncthreads();   // sred reads done before next block's epilogue writes
    }
}

// ---------------------------------------------------------------------------
// Phase 2: g_sum[b] = sum_t exp(ait[b,t]),  ait = p0 + p1
// ---------------------------------------------------------------------------
__global__ void __launch_bounds__(256) k_softsum()
{
    __shared__ float red[256];
    const int b = blockIdx.x, tid = threadIdx.x;
    float s = 0.f;
    for (int i = tid; i < T_LEN; i += 256) {
        const int r = b * T_LEN + i;
        s += expf(g_aitp[0][r] + g_aitp[1][r]);
    }
    red[tid] = s;
    __syncthreads();
    for (int off = 128; off > 0; off >>= 1) {
        if (tid < off) red[tid] += red[tid + off];
        __syncthreads();
    }
    if (tid == 0) g_sum[b] = red[0];
}

// ---------------------------------------------------------------------------
// Phase 3: partial weighted sums over 128-t chunks (float4, deterministic)
// ---------------------------------------------------------------------------
__global__ void __launch_bounds__(256) k_wsum(const float* __restrict__ x)
{
    __shared__ float  as[128];
    __shared__ float4 sp[256];
    const int chunk = blockIdx.x, b = blockIdx.y, tid = threadIdx.x;
    const int t0 = chunk * 128;
    const float inv = 1.f / (g_sum[b] + 1e-7f);
    if (tid < 128) {
        const int r = b * T_LEN + t0 + tid;
        as[tid] = expf(g_aitp[0][r] + g_aitp[1][r]) * inv;
    }
    __syncthreads();

    const int f4 = tid & 63, ts = tid >> 6;
    const float4* xb = reinterpret_cast<const float4*>(
        x + ((long)(b * T_LEN + t0)) * F_DIM);
    float4 acc = make_float4(0.f, 0.f, 0.f, 0.f);
    #pragma unroll 8
    for (int tt = ts; tt < 128; tt += 4) {
        const float4 v = xb[tt * 64 + f4];
        const float  a = as[tt];
        acc.x = fmaf(v.x, a, acc.x);
        acc.y = fmaf(v.y, a, acc.y);
        acc.z = fmaf(v.z, a, acc.z);
        acc.w = fmaf(v.w, a, acc.w);
    }
    sp[ts * 64 + f4] = acc;
    __syncthreads();
    if (ts == 0) {
        const float4 a0 = sp[f4], a1 = sp[64 + f4], a2 = sp[128 + f4], a3 = sp[192 + f4];
        float4 r;
        r.x = (a0.x + a1.x) + (a2.x + a3.x);
        r.y = (a0.y + a1.y) + (a2.y + a3.y);
        r.z = (a0.z + a1.z) + (a2.z + a3.z);
        r.w = (a0.w + a1.w) + (a2.w + a3.w);
        reinterpret_cast<float4*>(g_part + (chunk * B_BATCH + b) * F_DIM)[f4] = r;
    }
}

// ---------------------------------------------------------------------------
// Phase 4: reduce 16 partials -> out[b,f] (float4)
// ---------------------------------------------------------------------------
__global__ void __launch_bounds__(64) k_red(float* __restrict__ out)
{
    const int b = blockIdx.x, tid = threadIdx.x;
    const float4* gp = reinterpret_cast<const float4*>(g_part);
    float4 s = make_float4(0.f, 0.f, 0.f, 0.f);
    #pragma unroll
    for (int c = 0; c < 16; c++) {
        const float4 v = gp[(c * B_BATCH + b) * 64 + tid];
        s.x += v.x; s.y += v.y; s.z += v.z; s.w += v.w;
    }
    reinterpret_cast<float4*>(out)[b * 64 + tid] = s;
}

// ---------------------------------------------------------------------------
extern "C" void kernel_launch(void* const* d_in, const int* in_sizes, int n_in,
                              void* d_out, int out_size)
{
    const float* x    = (const float*)d_in[0];
    const float* W    = (const float*)d_in[1];
    const float* bias = (const float*)d_in[2];
    const float* u    = (const float*)d_in[3];
    float* out = (float*)d_out;

    cudaFuncSetAttribute(k_ait, cudaFuncAttributeMaxDynamicSharedMemorySize, SMEM_BYTES);

    k_wt<<<dim3(8, 8), dim3(32, 8)>>>(W);
    k_ait<<<NCTA, 256, SMEM_BYTES>>>(x, bias, u);   // persistent, N-split halves
    k_softsum<<<B_BATCH, 256>>>();
    k_wsum<<<dim3(16, B_BATCH), 256>>>(x);
    k_red<<<B_BATCH, 64>>>(out);
}